// round 14
// baseline (speedup 1.0000x reference)
#include <cuda_runtime.h>
#include <cuda_fp16.h>
#include <cstdint>
#include <math.h>

#define NTOK 8192
#define NE   8
#define DDIM 1024
#define HDIM 5632
#define H2   (2*HDIM)
#define CAP  1280

#define OUT_AUX  8388608
#define OUT_TOP  (8388608 + 1)
#define OUT_KEEP (8388608 + 1 + NTOK)

// fused-kernel schedule constants
#define NB1    88                  // gemm1 n-tiles (HDIM/64)
#define SG_LEN 1020                // 44 cvt13 + 16 cvt2 + 80 gemm2 + 880 gemm1
#define NSUPER 9
#define NTICK  (SG_LEN * NSUPER)
#define C13E   (H2 * DDIM)         // 11,534,336 halfs per expert
#define C2E    (DDIM * HDIM)       //  5,767,168 halfs per expert
#define C13CH  262144              // halfs per cvt13 chunk (x44)
#define C2CH   360448              // halfs per cvt2 chunk (x16)

// ---------------- scratch ----------------
__device__ float d_probs[NTOK * NE];
__device__ float d_z2[NTOK];
__device__ int   d_top[NTOK];
__device__ int   d_keep[NTOK];
__device__ int   d_gidx[NE * CAP];
__device__ int   d_counts[NE];
__device__ int   d_counts_cap[NE];
__device__ __align__(256) __half d_hh[(size_t)NE * CAP * HDIM];     // 115 MB
__device__ __align__(256) __half d_xh[(size_t)NTOK * DDIM];         //  17 MB
__device__ __align__(256) __half d_w13h[(size_t)NE * H2 * DDIM];    // 184 MB
__device__ __align__(256) __half d_w2h[(size_t)NE * DDIM * HDIM];   //  92 MB
// scheduler state (reset by scan_kernel each call)
__device__ unsigned int d_ticket;
__device__ unsigned int d_w13done[NE];
__device__ unsigned int d_w2done[NE];
__device__ unsigned int d_hdone[NE * 10];

// ---------------- helpers ----------------
__device__ __forceinline__ uint32_t smem_u32(const void* p) {
    uint32_t a;
    asm("{ .reg .u64 t; cvta.to.shared.u64 t, %1; cvt.u32.u64 %0, t; }"
        : "=r"(a) : "l"(p));
    return a;
}
__device__ __forceinline__ uint32_t h2_u32(__half2 h) {
    return *reinterpret_cast<uint32_t*>(&h);
}
__device__ __forceinline__ void mma_f16(float* c, const uint32_t* a,
                                        uint32_t b0, uint32_t b1) {
    asm volatile(
        "mma.sync.aligned.m16n8k16.row.col.f32.f16.f16.f32 "
        "{%0,%1,%2,%3}, {%4,%5,%6,%7}, {%8,%9}, {%0,%1,%2,%3};"
        : "+f"(c[0]), "+f"(c[1]), "+f"(c[2]), "+f"(c[3])
        : "r"(a[0]), "r"(a[1]), "r"(a[2]), "r"(a[3]), "r"(b0), "r"(b1));
}
#define LDSM4(r0, r1, r2, r3, a) \
    asm volatile("ldmatrix.sync.aligned.m8n8.x4.shared.b16 {%0,%1,%2,%3}, [%4];" \
                 : "=r"(r0), "=r"(r1), "=r"(r2), "=r"(r3) : "r"(a))
#define CP16(d, s) \
    asm volatile("cp.async.cg.shared.global [%0], [%1], 16;" :: "r"(d), "l"(s))
#define CPCOMMIT() asm volatile("cp.async.commit_group;")
#define CPWAIT1()  asm volatile("cp.async.wait_group 1;")

__device__ __forceinline__ void spin_ge(const unsigned int* p, unsigned int tgt) {
    volatile const unsigned int* vp = p;
    while (*vp < tgt) __nanosleep(64);
}

// ---------------- 0. fp32 -> fp16 conversion (x only) ----------------
__global__ void cvt_kernel(const float4* __restrict__ src,
                           uint2* __restrict__ dst, int n4)
{
    int i = blockIdx.x * blockDim.x + threadIdx.x;
    if (i < n4) {
        float4 v = src[i];
        __half2 lo = __floats2half2_rn(v.x, v.y);
        __half2 hi = __floats2half2_rn(v.z, v.w);
        dst[i] = make_uint2(h2_u32(lo), h2_u32(hi));
    }
}

// ---------------- 1. router ----------------
__global__ void router_kernel(const float* __restrict__ x,
                              const float* __restrict__ Wg)
{
    __shared__ float sWg[NE * DDIM];
    int t = threadIdx.x;
    for (int i = t; i < NE * DDIM; i += 256) sWg[i] = Wg[i];
    __syncthreads();

    int warp = t >> 5, lane = t & 31;
    int tok  = blockIdx.x * 8 + warp;
    const float* xr = x + (size_t)tok * DDIM;

    float acc[NE];
#pragma unroll
    for (int e = 0; e < NE; e++) acc[e] = 0.f;
    for (int k = lane; k < DDIM; k += 32) {
        float xv = xr[k];
#pragma unroll
        for (int e = 0; e < NE; e++) acc[e] = fmaf(xv, sWg[e * DDIM + k], acc[e]);
    }
#pragma unroll
    for (int e = 0; e < NE; e++) {
#pragma unroll
        for (int o = 16; o > 0; o >>= 1)
            acc[e] += __shfl_down_sync(0xffffffffu, acc[e], o);
    }
    if (lane == 0) {
        float m = acc[0]; int am = 0;
#pragma unroll
        for (int e = 1; e < NE; e++) if (acc[e] > m) { m = acc[e]; am = e; }
        float p[NE]; float s = 0.f;
#pragma unroll
        for (int e = 0; e < NE; e++) { p[e] = expf(acc[e] - m); s += p[e]; }
        float inv = 1.f / s;
#pragma unroll
        for (int e = 0; e < NE; e++) d_probs[tok * NE + e] = p[e] * inv;
        float z = m + logf(s);
        d_z2[tok] = z * z;
        d_top[tok] = am;
    }
}

// ---------------- 2. ordered capacity scan + scheduler reset ----------------
__global__ void scan_kernel()
{
    __shared__ unsigned long long wsum0[32], wsum1[32];
    __shared__ unsigned long long tile0, tile1;
    __shared__ int base[NE];
    const int t = threadIdx.x, lane = t & 31, wid = t >> 5;
    if (t < NE) base[t] = 0;
    if (t == 0) d_ticket = 0;
    if (t < NE) { d_w13done[t] = 0; d_w2done[t] = 0; }
    if (t < NE * 10) d_hdone[t] = 0;
    __syncthreads();

    for (int tile = 0; tile < NTOK / 1024; tile++) {
        int i = tile * 1024 + t;
        int e = d_top[i];
        unsigned long long v0 = (e < 4)  ? (1ULL << (16 * e))       : 0ULL;
        unsigned long long v1 = (e >= 4) ? (1ULL << (16 * (e - 4))) : 0ULL;
        unsigned long long s0 = v0, s1 = v1;
#pragma unroll
        for (int o = 1; o < 32; o <<= 1) {
            unsigned long long a0 = __shfl_up_sync(0xffffffffu, s0, o);
            unsigned long long a1 = __shfl_up_sync(0xffffffffu, s1, o);
            if (lane >= o) { s0 += a0; s1 += a1; }
        }
        if (lane == 31) { wsum0[wid] = s0; wsum1[wid] = s1; }
        __syncthreads();
        if (wid == 0) {
            unsigned long long w0 = wsum0[lane], w1 = wsum1[lane];
            unsigned long long p0 = w0, p1 = w1;
#pragma unroll
            for (int o = 1; o < 32; o <<= 1) {
                unsigned long long a0 = __shfl_up_sync(0xffffffffu, p0, o);
                unsigned long long a1 = __shfl_up_sync(0xffffffffu, p1, o);
                if (lane >= o) { p0 += a0; p1 += a1; }
            }
            wsum0[lane] = p0 - w0;
            wsum1[lane] = p1 - w1;
            if (lane == 31) { tile0 = p0; tile1 = p1; }
        }
        __syncthreads();
        unsigned long long inc = (e < 4) ? (s0 + wsum0[wid]) : (s1 + wsum1[wid]);
        int sh  = 16 * (e & 3);
        int pos = base[e] + (int)((inc >> sh) & 0xFFFFULL) - 1;
        int kp  = (pos < CAP) ? 1 : 0;
        d_keep[i] = kp;
        if (kp) d_gidx[e * CAP + pos] = i;
        __syncthreads();
        if (t < 4)      base[t] += (int)((tile0 >> (16 * t)) & 0xFFFFULL);
        else if (t < 8) base[t] += (int)((tile1 >> (16 * (t - 4))) & 0xFFFFULL);
        __syncthreads();
    }
    if (t < NE) {
        d_counts[t] = base[t];
        d_counts_cap[t] = base[t] < CAP ? base[t] : CAP;
    }
}

// ---------------- 3. aux loss ----------------
__global__ void reduce_kernel(float* __restrict__ out_aux)
{
    __shared__ float sm[1024];
    __shared__ float pe[NE];
    int t = threadIdx.x;
    float pp[NE];
#pragma unroll
    for (int e = 0; e < NE; e++) pp[e] = 0.f;
    float zz = 0.f;
    for (int i = t; i < NTOK; i += 1024) {
#pragma unroll
        for (int e = 0; e < NE; e++) pp[e] += d_probs[i * NE + e];
        zz += d_z2[i];
    }
#pragma unroll
    for (int e = 0; e < NE; e++) {
        sm[t] = pp[e]; __syncthreads();
        for (int o = 512; o > 0; o >>= 1) {
            if (t < o) sm[t] += sm[t + o];
            __syncthreads();
        }
        if (t == 0) pe[e] = sm[0];
        __syncthreads();
    }
    sm[t] = zz; __syncthreads();
    for (int o = 512; o > 0; o >>= 1) {
        if (t < o) sm[t] += sm[t + o];
        __syncthreads();
    }
    if (t == 0) {
        float bal = 0.f;
        for (int e = 0; e < NE; e++)
            bal += (pe[e] / (float)NTOK) * ((float)d_counts[e] / (float)NTOK);
        bal *= 0.01f * (float)NE;
        out_aux[0] = bal + (sm[0] / (float)NTOK) * 0.001f;
    }
}

// ---------------- 4. fused persistent MoE kernel ---------------------------
// Ticket schedule per supergroup s (s = 0..8):
//   [   0,  44): w13 cvt chunk (expert s)          -> d_w13done[s]++
//   [  44,  60): w2  cvt chunk (expert s)          -> d_w2done[s]++
//   [  60, 140): gemm2 tile (expert s-1)            waits w2done=16, hdone=88
//   [ 140,1020): gemm1 tile (expert s), 88 nb x 10 mb; -> hdone[e,mb]++
// Deadlock-free: tickets dispensed in order; a spinning consumer's producers
// were dispensed earlier, are owned by running CTAs, and terminate (cvt has
// no deps; gemm1 deps only cvt).
#define STG_B  32768
#define SMEM_G (3 * STG_B)

__global__ __launch_bounds__(256, 2)
void moe_fused(const float* __restrict__ W13, const float* __restrict__ W2,
               float* __restrict__ out)
{
    extern __shared__ char smc[];
    __shared__ int s_tok[128];
    __shared__ unsigned int s_tk;

    const int t = threadIdx.x, lane = t & 31;
    const int lc = lane & 3;
    const int wid = t >> 5;
    const int warpM = wid & 3, warpN = wid >> 2;
    const uint32_t sbase = smem_u32(smc);
    const int lrow = t >> 1;
    const int q0l  = (t & 1) * 4;
    const int rA   = warpM * 32 + (lane & 15);
    const int cselA = lane >> 4;
    const int rB   = (lane & 7) + ((lane & 16) >> 1);
    const int cselB = (lane >> 3) & 1;
    const int lr   = lane >> 2;

    for (;;) {
        __syncthreads();
        if (t == 0) s_tk = atomicAdd(&d_ticket, 1u);
        __syncthreads();
        const unsigned int tk = s_tk;
        if (tk >= NTICK) break;
        const int sg  = tk / SG_LEN;
        const int sub = tk % SG_LEN;

        // ---- conversion tickets ----
        if (sub < 60) {
            if (sg >= NE) continue;
            const float4* src;
            uint4* dst;
            int n16;
            unsigned int* ctr;
            if (sub < 44) {
                size_t off = (size_t)sg * C13E + (size_t)sub * C13CH;
                src = (const float4*)(W13 + off);
                dst = (uint4*)(d_w13h + off);
                n16 = C13CH / 8;
                ctr = &d_w13done[sg];
            } else {
                size_t off = (size_t)sg * C2E + (size_t)(sub - 44) * C2CH;
                src = (const float4*)(W2 + off);
                dst = (uint4*)(d_w2h + off);
                n16 = C2CH / 8;
                ctr = &d_w2done[sg];
            }
            for (int i = t; i < n16; i += 256) {
                float4 a = src[2 * i], b = src[2 * i + 1];
                uint4 o;
                o.x = h2_u32(__floats2half2_rn(a.x, a.y));
                o.y = h2_u32(__floats2half2_rn(a.z, a.w));
                o.z = h2_u32(__floats2half2_rn(b.x, b.y));
                o.w = h2_u32(__floats2half2_rn(b.z, b.w));
                dst[i] = o;
            }
            __threadfence();
            __syncthreads();
            if (t == 0) atomicAdd(ctr, 1u);
            continue;
        }

        // ---- GEMM tickets ----
        int mode, e, mb, nb;
        if (sub < 140) {                   // gemm2(expert sg-1): 8 nb x 10 mb
            if (sg < 1) continue;
            mode = 1; e = sg - 1;
            int idx = sub - 60;
            nb = idx / 10; mb = idx % 10;
        } else {                           // gemm1(expert sg): 88 nb x 10 mb
            if (sg >= NE) continue;
            mode = 0; e = sg;
            int idx = sub - 140;
            nb = idx / 10; mb = idx % 10;
        }

        const int cc = d_counts_cap[e];
        const int m0 = mb * 128;
        const bool dead = (m0 >= cc);

        if (!dead) {
            if (t == 0) {
                if (mode == 0) {
                    spin_ge(&d_w13done[e], 44);
                } else {
                    spin_ge(&d_w2done[e], 16);
                    spin_ge(&d_hdone[e * 10 + mb], NB1);
                }
            }
            __syncthreads();

            if (t < 128)
                s_tok[t] = (m0 + t < cc) ? d_gidx[e * CAP + m0 + t]
                                         : ((mode == 0) ? 0 : -1);
            __syncthreads();

            const int KT  = (mode == 0) ? DDIM / 64 : HDIM / 64;
            const int WNS = (mode == 0) ? 32 : 64;
            const int NO2 = (mode == 0) ? 64 : 32;

            auto load_stage = [&](int kt, int s) {
                const uint32_t ab = sbase + (uint32_t)s * STG_B;
                const uint32_t bb = ab + 16384;
                const int k0 = kt * 64;
#pragma unroll
                for (int c = 0; c < 4; c++) {
                    int q = q0l + c;
                    uint32_t dsw = (uint32_t)(lrow * 128 + ((q ^ (lrow & 7)) << 4));
                    const __half* srcA;
                    if (mode == 0)
                        srcA = d_xh + (size_t)s_tok[lrow] * DDIM + k0 + q * 8;
                    else
                        srcA = d_hh + ((size_t)e * CAP + m0 + lrow) * HDIM + k0 + q * 8;
                    CP16(ab + dsw, srcA);
                    const __half* srcB;
                    if (mode == 0) {
                        int wr = (lrow < 64) ? (nb * 64 + lrow)
                                             : (HDIM + nb * 64 + lrow - 64);
                        srcB = d_w13h + ((size_t)e * H2 + wr) * DDIM + k0 + q * 8;
                    } else {
                        srcB = d_w2h + ((size_t)e * DDIM + nb * 128 + lrow) * HDIM + k0 + q * 8;
                    }
                    CP16(bb + dsw, srcB);
                }
            };

            float c0[2][4][4], c1[2][4][4];
#pragma unroll
            for (int a = 0; a < 2; a++)
#pragma unroll
                for (int b = 0; b < 4; b++)
#pragma unroll
                    for (int r = 0; r < 4; r++) { c0[a][b][r] = 0.f; c1[a][b][r] = 0.f; }

            load_stage(0, 0); CPCOMMIT();
            load_stage(1, 1); CPCOMMIT();

            for (int kt = 0; kt < KT; kt++) {
                CPWAIT1();
                __syncthreads();
                if (kt + 2 < KT) load_stage(kt + 2, (kt + 2) % 3);
                CPCOMMIT();

                const uint32_t ab = sbase + (uint32_t)(kt % 3) * STG_B;
                const uint32_t bb = ab + 16384;
#pragma unroll
                for (int kk = 0; kk < 4; kk++) {
                    uint32_t a[2][4];
#pragma unroll
                    for (int mf = 0; mf < 2; mf++) {
                        int r = rA + mf * 16;
                        uint32_t ad = ab + r * 128 + (((kk * 2 + cselA) ^ (r & 7)) << 4);
                        LDSM4(a[mf][0], a[mf][1], a[mf][2], a[mf][3], ad);
                    }
#pragma unroll
                    for (int p = 0; p < 2; p++) {
                        int r0n = warpN * WNS + p * 16 + rB;
                        uint32_t bd0 = bb + r0n * 128 + (((kk * 2 + cselB) ^ (r0n & 7)) << 4);
                        uint32_t g0, g1, g2, g3;
                        LDSM4(g0, g1, g2, g3, bd0);
                        int r1n = r0n + NO2;
                        uint32_t bd1 = bb + r1n * 128 + (((kk * 2 + cselB) ^ (r1n & 7)) << 4);
                        uint32_t u0, u1, u2, u3;
                        LDSM4(u0, u1, u2, u3, bd1);
#pragma unroll
                        for (int mf = 0; mf < 2; mf++) {
                            mma_f16(c0[mf][2 * p],     a[mf], g0, g1);
                            mma_f16(c0[mf][2 * p + 1], a[mf], g2, g3);
                            mma_f16(c1[mf][2 * p],     a[mf], u0, u1);
                            mma_f16(c1[mf][2 * p + 1], a[mf], u2, u3);
                        }
                    }
                }
            }

            if (mode == 0) {
#pragma unroll
                for (int mf = 0; mf < 2; mf++) {
                    int r0 = m0 + warpM * 32 + mf * 16 + lr;
#pragma unroll
                    for (int nf = 0; nf < 4; nf++) {
                        int col = nb * 64 + warpN * 32 + nf * 8 + 2 * lc;
#pragma unroll
                        for (int hh = 0; hh < 2; hh++) {
                            float g0 = c0[mf][nf][2 * hh], g1 = c0[mf][nf][2 * hh + 1];
                            float u0 = c1[mf][nf][2 * hh], u1 = c1[mf][nf][2 * hh + 1];
                            float h0 = g0 * u0 / (1.f + expf(-g0));
                            float h1 = g1 * u1 / (1.f + expf(-g1));
                            __half2 hv = __floats2half2_rn(h0, h1);
                            *(__half2*)(d_hh + ((size_t)e * CAP + r0 + 8 * hh) * HDIM + col) = hv;
                        }
                    }
                }
            } else {
#pragma unroll
                for (int mf = 0; mf < 2; mf++) {
                    int rl = warpM * 32 + mf * 16 + lr;
                    int tok0 = s_tok[rl], tok1 = s_tok[rl + 8];
#pragma unroll
                    for (int nf = 0; nf < 4; nf++) {
                        int colA = nb * 128 + warpN * 64 + nf * 8 + 2 * lc;
                        int colB = colA + 32;
                        if (tok0 >= 0) {
                            *(float2*)(out + (size_t)tok0 * DDIM + colA) =
                                make_float2(c0[mf][nf][0], c0[mf][nf][1]);
                            *(float2*)(out + (size_t)tok0 * DDIM + colB) =
                                make_float2(c1[mf][nf][0], c1[mf][nf][1]);
                        }
                        if (tok1 >= 0) {
                            *(float2*)(out + (size_t)tok1 * DDIM + colA) =
                                make_float2(c0[mf][nf][2], c0[mf][nf][3]);
                            *(float2*)(out + (size_t)tok1 * DDIM + colB) =
                                make_float2(c1[mf][nf][2], c1[mf][nf][3]);
                        }
                    }
                }
            }
        }

        if (mode == 0) {                   // gemm1 signals h completion (even dead)
            __threadfence();
            __syncthreads();
            if (t == 0) atomicAdd(&d_hdone[e * 10 + mb], 1u);
        }
    }
}

// ---------------- 6. finalize ----------------
__global__ void finalize_kernel(float* __restrict__ out)
{
    int i = blockIdx.x, t = threadIdx.x;
    int kp = d_keep[i];
    if (!kp)
        ((float4*)(out + (size_t)i * DDIM))[t] = make_float4(0.f, 0.f, 0.f, 0.f);
    if (t == 0) {
        out[OUT_TOP + i]  = (float)d_top[i];
        out[OUT_KEEP + i] = kp ? 1.f : 0.f;
    }
}

// ---------------- launch ----------------
extern "C" void kernel_launch(void* const* d_in, const int* in_sizes, int n_in,
                              void* d_out, int out_size)
{
    const float* x   = (const float*)d_in[0];
    const float* Wg  = (const float*)d_in[1];
    const float* W13 = (const float*)d_in[2];
    const float* W2  = (const float*)d_in[3];
    float* out = (float*)d_out;

    cudaFuncSetAttribute(moe_fused, cudaFuncAttributeMaxDynamicSharedMemorySize, SMEM_G);

    __half* xh; cudaGetSymbolAddress((void**)&xh, d_xh);
    const int n4x = NTOK * DDIM / 4;

    cudaStream_t s2;
    cudaEvent_t evFork, evJoin, evEnd;
    cudaStreamCreateWithFlags(&s2, cudaStreamNonBlocking);
    cudaEventCreateWithFlags(&evFork, cudaEventDisableTiming);
    cudaEventCreateWithFlags(&evJoin, cudaEventDisableTiming);
    cudaEventCreateWithFlags(&evEnd,  cudaEventDisableTiming);

    cudaEventRecord(evFork, 0);
    cudaStreamWaitEvent(s2, evFork, 0);

    // side stream: token path (+ scheduler reset inside scan), then small kernels
    cvt_kernel<<<(n4x + 255) / 256, 256, 0, s2>>>((const float4*)x, (uint2*)xh, n4x);
    router_kernel<<<NTOK / 8, 256, 0, s2>>>(x, Wg);
    scan_kernel<<<1, 1024, 0, s2>>>();
    cudaEventRecord(evJoin, s2);
    reduce_kernel<<<1, 1024, 0, s2>>>(out + OUT_AUX);
    finalize_kernel<<<NTOK, 256, 0, s2>>>(out);
    cudaEventRecord(evEnd, s2);

    // main stream: fused persistent kernel (cvt + gemm1 + gemm2 via tickets)
    cudaStreamWaitEvent(0, evJoin, 0);
    moe_fused<<<304, 256, SMEM_G>>>(W13, W2, out);
    cudaStreamWaitEvent(0, evEnd, 0);

    cudaEventDestroy(evFork);
    cudaEventDestroy(evJoin);
    cudaEventDestroy(evEnd);
    cudaStreamDestroy(s2);
}

// round 15
// speedup vs baseline: 1.4493x; 1.4493x over previous
#include <cuda_runtime.h>
#include <cuda_fp16.h>
#include <cstdint>
#include <math.h>

#define NTOK 8192
#define NE   8
#define DDIM 1024
#define HDIM 5632
#define H2   (2*HDIM)
#define CAP  1280

#define OUT_AUX  8388608
#define OUT_TOP  (8388608 + 1)
#define OUT_KEEP (8388608 + 1 + NTOK)

#define W13_BLKS_PER_E 11264       // cvt13 blocks per expert (256 float4 each)

// ---------------- scratch ----------------
__device__ float d_probs[NTOK * NE];
__device__ float d_z2[NTOK];
__device__ int   d_top[NTOK];
__device__ int   d_keep[NTOK];
__device__ int   d_gidx[NE * CAP];
__device__ int   d_counts[NE];
__device__ int   d_counts_cap[NE];
__device__ unsigned int d_w13done[NE];
__device__ __align__(256) __half d_hh[(size_t)NE * CAP * HDIM];     // 115 MB
__device__ __align__(256) __half d_xh[(size_t)NTOK * DDIM];         //  17 MB
__device__ __align__(256) __half d_w13h[(size_t)NE * H2 * DDIM];    // 184 MB
__device__ __align__(256) __half d_w2h[(size_t)NE * DDIM * HDIM];   //  92 MB

// ---------------- helpers ----------------
__device__ __forceinline__ uint32_t smem_u32(const void* p) {
    uint32_t a;
    asm("{ .reg .u64 t; cvta.to.shared.u64 t, %1; cvt.u32.u64 %0, t; }"
        : "=r"(a) : "l"(p));
    return a;
}
__device__ __forceinline__ uint32_t h2_u32(__half2 h) {
    return *reinterpret_cast<uint32_t*>(&h);
}
__device__ __forceinline__ void mma_f16(float* c, const uint32_t* a,
                                        uint32_t b0, uint32_t b1) {
    asm volatile(
        "mma.sync.aligned.m16n8k16.row.col.f32.f16.f16.f32 "
        "{%0,%1,%2,%3}, {%4,%5,%6,%7}, {%8,%9}, {%0,%1,%2,%3};"
        : "+f"(c[0]), "+f"(c[1]), "+f"(c[2]), "+f"(c[3])
        : "r"(a[0]), "r"(a[1]), "r"(a[2]), "r"(a[3]), "r"(b0), "r"(b1));
}
#define LDSM4(r0, r1, r2, r3, a) \
    asm volatile("ldmatrix.sync.aligned.m8n8.x4.shared.b16 {%0,%1,%2,%3}, [%4];" \
                 : "=r"(r0), "=r"(r1), "=r"(r2), "=r"(r3) : "r"(a))
#define CP16(d, s) \
    asm volatile("cp.async.cg.shared.global [%0], [%1], 16;" :: "r"(d), "l"(s))
#define CPCOMMIT() asm volatile("cp.async.commit_group;")
#define CPWAIT1()  asm volatile("cp.async.wait_group 1;")

// ---------------- 0a. scheduler reset ----------------
__global__ void reset_kernel()
{
    if (threadIdx.x < NE) d_w13done[threadIdx.x] = 0;
}

// ---------------- 0b. fp32 -> fp16 conversion ----------------
__global__ void cvt_kernel(const float4* __restrict__ src,
                           uint2* __restrict__ dst, int n4)
{
    int i = blockIdx.x * blockDim.x + threadIdx.x;
    if (i < n4) {
        float4 v = src[i];
        __half2 lo = __floats2half2_rn(v.x, v.y);
        __half2 hi = __floats2half2_rn(v.z, v.w);
        dst[i] = make_uint2(h2_u32(lo), h2_u32(hi));
    }
}

// W13 conversion with per-expert completion counters (grid ordered by expert)
__global__ void cvt13_kernel(const float4* __restrict__ src,
                             uint2* __restrict__ dst)
{
    int i = blockIdx.x * 256 + threadIdx.x;
    float4 v = src[i];
    __half2 lo = __floats2half2_rn(v.x, v.y);
    __half2 hi = __floats2half2_rn(v.z, v.w);
    dst[i] = make_uint2(h2_u32(lo), h2_u32(hi));
    __threadfence();
    __syncthreads();
    if (threadIdx.x == 0)
        atomicAdd(&d_w13done[blockIdx.x / W13_BLKS_PER_E], 1u);
}

// ---------------- 1. router ----------------
__global__ void router_kernel(const float* __restrict__ x,
                              const float* __restrict__ Wg)
{
    __shared__ float sWg[NE * DDIM];
    int t = threadIdx.x;
    for (int i = t; i < NE * DDIM; i += 256) sWg[i] = Wg[i];
    __syncthreads();

    int warp = t >> 5, lane = t & 31;
    int tok  = blockIdx.x * 8 + warp;
    const float* xr = x + (size_t)tok * DDIM;

    float acc[NE];
#pragma unroll
    for (int e = 0; e < NE; e++) acc[e] = 0.f;
    for (int k = lane; k < DDIM; k += 32) {
        float xv = xr[k];
#pragma unroll
        for (int e = 0; e < NE; e++) acc[e] = fmaf(xv, sWg[e * DDIM + k], acc[e]);
    }
#pragma unroll
    for (int e = 0; e < NE; e++) {
#pragma unroll
        for (int o = 16; o > 0; o >>= 1)
            acc[e] += __shfl_down_sync(0xffffffffu, acc[e], o);
    }
    if (lane == 0) {
        float m = acc[0]; int am = 0;
#pragma unroll
        for (int e = 1; e < NE; e++) if (acc[e] > m) { m = acc[e]; am = e; }
        float p[NE]; float s = 0.f;
#pragma unroll
        for (int e = 0; e < NE; e++) { p[e] = expf(acc[e] - m); s += p[e]; }
        float inv = 1.f / s;
#pragma unroll
        for (int e = 0; e < NE; e++) d_probs[tok * NE + e] = p[e] * inv;
        float z = m + logf(s);
        d_z2[tok] = z * z;
        d_top[tok] = am;
    }
}

// ---------------- 2. ordered capacity scan (shfl-based) ----------------
__global__ void scan_kernel()
{
    __shared__ unsigned long long wsum0[32], wsum1[32];
    __shared__ unsigned long long tile0, tile1;
    __shared__ int base[NE];
    const int t = threadIdx.x, lane = t & 31, wid = t >> 5;
    if (t < NE) base[t] = 0;
    __syncthreads();

    for (int tile = 0; tile < NTOK / 1024; tile++) {
        int i = tile * 1024 + t;
        int e = d_top[i];
        unsigned long long v0 = (e < 4)  ? (1ULL << (16 * e))       : 0ULL;
        unsigned long long v1 = (e >= 4) ? (1ULL << (16 * (e - 4))) : 0ULL;
        unsigned long long s0 = v0, s1 = v1;
#pragma unroll
        for (int o = 1; o < 32; o <<= 1) {
            unsigned long long a0 = __shfl_up_sync(0xffffffffu, s0, o);
            unsigned long long a1 = __shfl_up_sync(0xffffffffu, s1, o);
            if (lane >= o) { s0 += a0; s1 += a1; }
        }
        if (lane == 31) { wsum0[wid] = s0; wsum1[wid] = s1; }
        __syncthreads();
        if (wid == 0) {
            unsigned long long w0 = wsum0[lane], w1 = wsum1[lane];
            unsigned long long p0 = w0, p1 = w1;
#pragma unroll
            for (int o = 1; o < 32; o <<= 1) {
                unsigned long long a0 = __shfl_up_sync(0xffffffffu, p0, o);
                unsigned long long a1 = __shfl_up_sync(0xffffffffu, p1, o);
                if (lane >= o) { p0 += a0; p1 += a1; }
            }
            wsum0[lane] = p0 - w0;       // exclusive warp offsets
            wsum1[lane] = p1 - w1;
            if (lane == 31) { tile0 = p0; tile1 = p1; }
        }
        __syncthreads();
        unsigned long long inc = (e < 4) ? (s0 + wsum0[wid]) : (s1 + wsum1[wid]);
        int sh  = 16 * (e & 3);
        int pos = base[e] + (int)((inc >> sh) & 0xFFFFULL) - 1;
        int kp  = (pos < CAP) ? 1 : 0;
        d_keep[i] = kp;
        if (kp) d_gidx[e * CAP + pos] = i;
        __syncthreads();
        if (t < 4)      base[t] += (int)((tile0 >> (16 * t)) & 0xFFFFULL);
        else if (t < 8) base[t] += (int)((tile1 >> (16 * (t - 4))) & 0xFFFFULL);
        __syncthreads();
    }
    if (t < NE) {
        d_counts[t] = base[t];
        d_counts_cap[t] = base[t] < CAP ? base[t] : CAP;
    }
}

// ---------------- 3. aux loss ----------------
__global__ void reduce_kernel(float* __restrict__ out_aux)
{
    __shared__ float sm[1024];
    __shared__ float pe[NE];
    int t = threadIdx.x;
    float pp[NE];
#pragma unroll
    for (int e = 0; e < NE; e++) pp[e] = 0.f;
    float zz = 0.f;
    for (int i = t; i < NTOK; i += 1024) {
#pragma unroll
        for (int e = 0; e < NE; e++) pp[e] += d_probs[i * NE + e];
        zz += d_z2[i];
    }
#pragma unroll
    for (int e = 0; e < NE; e++) {
        sm[t] = pp[e]; __syncthreads();
        for (int o = 512; o > 0; o >>= 1) {
            if (t < o) sm[t] += sm[t + o];
            __syncthreads();
        }
        if (t == 0) pe[e] = sm[0];
        __syncthreads();
    }
    sm[t] = zz; __syncthreads();
    for (int o = 512; o > 0; o >>= 1) {
        if (t < o) sm[t] += sm[t + o];
        __syncthreads();
    }
    if (t == 0) {
        float bal = 0.f;
        for (int e = 0; e < NE; e++)
            bal += (pe[e] / (float)NTOK) * ((float)d_counts[e] / (float)NTOK);
        bal *= 0.01f * (float)NE;
        out_aux[0] = bal + (sm[0] / (float)NTOK) * 0.001f;
    }
}

// ---------------- 4/5. fp16 mma.sync GEMMs (identical hot loop to R12) ----
// MODE 0 spins (t0 only) on d_w13done[e] so it can launch before the W13
// conversion finishes; cvt runs concurrently on the other stream and stays
// ahead (cvt/expert ~27us vs gemm1/expert ~81us).
#define STG_B  32768
#define SMEM_G (3 * STG_B)

template<int MODE>
__global__ __launch_bounds__(256, 2)
void moe_gemm(float* __restrict__ out)
{
    constexpr int KT  = (MODE == 0) ? DDIM / 64 : HDIM / 64;
    constexpr int WNS = (MODE == 0) ? 32 : 64;
    constexpr int NO2 = (MODE == 0) ? 64 : 32;

    extern __shared__ char smc[];
    __shared__ int s_tok[128];

    const int t = threadIdx.x, wid = t >> 5, lane = t & 31;
    const int lc = lane & 3;
    const int warpM = wid & 3, warpN = wid >> 2;
    const int e = blockIdx.z, m0 = blockIdx.x * 128, nb = blockIdx.y;

    const int cc = d_counts_cap[e];
    if (m0 >= cc) return;

    if (t < 128)
        s_tok[t] = (m0 + t < cc) ? d_gidx[e * CAP + m0 + t] : ((MODE == 0) ? 0 : -1);
    if (MODE == 0 && t == 0) {
        volatile const unsigned int* vp = &d_w13done[e];
        while (*vp < W13_BLKS_PER_E) __nanosleep(128);
    }
    __syncthreads();

    const uint32_t sbase = smem_u32(smc);
    const int lrow = t >> 1;
    const int q0l  = (t & 1) * 4;

    auto load_stage = [&](int kt, int s) {
        const uint32_t ab = sbase + (uint32_t)s * STG_B;
        const uint32_t bb = ab + 16384;
        const int k0 = kt * 64;
#pragma unroll
        for (int c = 0; c < 4; c++) {
            int q = q0l + c;
            uint32_t dsw = (uint32_t)(lrow * 128 + ((q ^ (lrow & 7)) << 4));
            const __half* srcA;
            if (MODE == 0)
                srcA = d_xh + (size_t)s_tok[lrow] * DDIM + k0 + q * 8;
            else
                srcA = d_hh + ((size_t)e * CAP + m0 + lrow) * HDIM + k0 + q * 8;
            CP16(ab + dsw, srcA);
            const __half* srcB;
            if (MODE == 0) {
                int wr = (lrow < 64) ? (nb * 64 + lrow)
                                     : (HDIM + nb * 64 + lrow - 64);
                srcB = d_w13h + ((size_t)e * H2 + wr) * DDIM + k0 + q * 8;
            } else {
                srcB = d_w2h + ((size_t)e * DDIM + nb * 128 + lrow) * HDIM + k0 + q * 8;
            }
            CP16(bb + dsw, srcB);
        }
    };

    float c0[2][4][4], c1[2][4][4];
#pragma unroll
    for (int a = 0; a < 2; a++)
#pragma unroll
        for (int b = 0; b < 4; b++)
#pragma unroll
            for (int r = 0; r < 4; r++) { c0[a][b][r] = 0.f; c1[a][b][r] = 0.f; }

    const int rA  = warpM * 32 + (lane & 15);
    const int cselA = lane >> 4;
    const int rB  = (lane & 7) + ((lane & 16) >> 1);
    const int cselB = (lane >> 3) & 1;

    load_stage(0, 0); CPCOMMIT();
    load_stage(1, 1); CPCOMMIT();

    for (int kt = 0; kt < KT; kt++) {
        CPWAIT1();
        __syncthreads();
        if (kt + 2 < KT) load_stage(kt + 2, (kt + 2) % 3);
        CPCOMMIT();

        const uint32_t ab = sbase + (uint32_t)(kt % 3) * STG_B;
        const uint32_t bb = ab + 16384;
#pragma unroll
        for (int kk = 0; kk < 4; kk++) {
            uint32_t a[2][4];
#pragma unroll
            for (int mf = 0; mf < 2; mf++) {
                int r = rA + mf * 16;
                uint32_t ad = ab + r * 128 + (((kk * 2 + cselA) ^ (r & 7)) << 4);
                LDSM4(a[mf][0], a[mf][1], a[mf][2], a[mf][3], ad);
            }
#pragma unroll
            for (int p = 0; p < 2; p++) {
                int r0n = warpN * WNS + p * 16 + rB;
                uint32_t bd0 = bb + r0n * 128 + (((kk * 2 + cselB) ^ (r0n & 7)) << 4);
                uint32_t g0, g1, g2, g3;
                LDSM4(g0, g1, g2, g3, bd0);
                int r1n = r0n + NO2;
                uint32_t bd1 = bb + r1n * 128 + (((kk * 2 + cselB) ^ (r1n & 7)) << 4);
                uint32_t u0, u1, u2, u3;
                LDSM4(u0, u1, u2, u3, bd1);
#pragma unroll
                for (int mf = 0; mf < 2; mf++) {
                    mma_f16(c0[mf][2 * p],     a[mf], g0, g1);
                    mma_f16(c0[mf][2 * p + 1], a[mf], g2, g3);
                    mma_f16(c1[mf][2 * p],     a[mf], u0, u1);
                    mma_f16(c1[mf][2 * p + 1], a[mf], u2, u3);
                }
            }
        }
    }

    const int lr = lane >> 2;
    if (MODE == 0) {
#pragma unroll
        for (int mf = 0; mf < 2; mf++) {
            int r0 = m0 + warpM * 32 + mf * 16 + lr;
#pragma unroll
            for (int nf = 0; nf < 4; nf++) {
                int col = nb * 64 + warpN * 32 + nf * 8 + 2 * lc;
#pragma unroll
                for (int hh = 0; hh < 2; hh++) {
                    float g0 = c0[mf][nf][2 * hh], g1 = c0[mf][nf][2 * hh + 1];
                    float u0 = c1[mf][nf][2 * hh], u1 = c1[mf][nf][2 * hh + 1];
                    float h0 = g0 * u0 / (1.f + expf(-g0));
                    float h1 = g1 * u1 / (1.f + expf(-g1));
                    __half2 hv = __floats2half2_rn(h0, h1);
                    *(__half2*)(d_hh + ((size_t)e * CAP + r0 + 8 * hh) * HDIM + col) = hv;
                }
            }
        }
    } else {
#pragma unroll
        for (int mf = 0; mf < 2; mf++) {
            int rl = warpM * 32 + mf * 16 + lr;
            int tok0 = s_tok[rl], tok1 = s_tok[rl + 8];
#pragma unroll
            for (int nf = 0; nf < 4; nf++) {
                int colA = nb * 128 + warpN * 64 + nf * 8 + 2 * lc;
                int colB = colA + 32;
                if (tok0 >= 0) {
                    *(float2*)(out + (size_t)tok0 * DDIM + colA) =
                        make_float2(c0[mf][nf][0], c0[mf][nf][1]);
                    *(float2*)(out + (size_t)tok0 * DDIM + colB) =
                        make_float2(c1[mf][nf][0], c1[mf][nf][1]);
                }
                if (tok1 >= 0) {
                    *(float2*)(out + (size_t)tok1 * DDIM + colA) =
                        make_float2(c0[mf][nf][2], c0[mf][nf][3]);
                    *(float2*)(out + (size_t)tok1 * DDIM + colB) =
                        make_float2(c1[mf][nf][2], c1[mf][nf][3]);
                }
            }
        }
    }
}

// ---------------- 6. finalize ----------------
__global__ void finalize_kernel(float* __restrict__ out)
{
    int i = blockIdx.x, t = threadIdx.x;
    int kp = d_keep[i];
    if (!kp)
        ((float4*)(out + (size_t)i * DDIM))[t] = make_float4(0.f, 0.f, 0.f, 0.f);
    if (t == 0) {
        out[OUT_TOP + i]  = (float)d_top[i];
        out[OUT_KEEP + i] = kp ? 1.f : 0.f;
    }
}

// ---------------- launch: gemm chain on side stream, cvt on main -----------
extern "C" void kernel_launch(void* const* d_in, const int* in_sizes, int n_in,
                              void* d_out, int out_size)
{
    const float* x   = (const float*)d_in[0];
    const float* Wg  = (const float*)d_in[1];
    const float* W13 = (const float*)d_in[2];
    const float* W2  = (const float*)d_in[3];
    float* out = (float*)d_out;

    cudaFuncSetAttribute(moe_gemm<0>, cudaFuncAttributeMaxDynamicSharedMemorySize, SMEM_G);
    cudaFuncSetAttribute(moe_gemm<1>, cudaFuncAttributeMaxDynamicSharedMemorySize, SMEM_G);

    __half* xh;   cudaGetSymbolAddress((void**)&xh,   d_xh);
    __half* w13h; cudaGetSymbolAddress((void**)&w13h, d_w13h);
    __half* w2h;  cudaGetSymbolAddress((void**)&w2h,  d_w2h);

    const int n4x  = NTOK * DDIM / 4;
    const int n4w1 = NE * H2 * DDIM / 4;   // 23,068,672 -> 90112 blocks
    const int n4w2 = NE * DDIM * HDIM / 4;

    cudaStream_t s2;
    cudaEvent_t evFork, evScan, evW2, evEnd;
    cudaStreamCreateWithFlags(&s2, cudaStreamNonBlocking);
    cudaEventCreateWithFlags(&evFork, cudaEventDisableTiming);
    cudaEventCreateWithFlags(&evScan, cudaEventDisableTiming);
    cudaEventCreateWithFlags(&evW2,   cudaEventDisableTiming);
    cudaEventCreateWithFlags(&evEnd,  cudaEventDisableTiming);

    // main: reset counters, then weight conversions (w13 feeds counters)
    reset_kernel<<<1, 32>>>();
    cudaEventRecord(evFork, 0);
    cudaStreamWaitEvent(s2, evFork, 0);

    cvt13_kernel<<<n4w1 / 256, 256>>>((const float4*)W13, (uint2*)w13h);
    cvt_kernel<<<(n4w2 + 255) / 256, 256>>>((const float4*)W2, (uint2*)w2h, n4w2);
    cudaEventRecord(evW2, 0);

    // side stream: token path, then both GEMMs (gemm1 spins on w13done)
    cvt_kernel<<<(n4x + 255) / 256, 256, 0, s2>>>((const float4*)x, (uint2*)xh, n4x);
    router_kernel<<<NTOK / 8, 256, 0, s2>>>(x, Wg);
    scan_kernel<<<1, 1024, 0, s2>>>();
    cudaEventRecord(evScan, s2);

    dim3 g1(CAP / 128, HDIM / 64, NE);          // 10 x 88 x 8
    moe_gemm<0><<<g1, 256, SMEM_G, s2>>>(nullptr);

    cudaStreamWaitEvent(s2, evW2, 0);
    dim3 g2(CAP / 128, DDIM / 128, NE);         // 10 x 8 x 8
    moe_gemm<1><<<g2, 256, SMEM_G, s2>>>(out);
    cudaEventRecord(evEnd, s2);

    // main: aux loss + finalize (need scan/probs), then join gemms
    cudaStreamWaitEvent(0, evScan, 0);
    reduce_kernel<<<1, 1024>>>(out + OUT_AUX);
    finalize_kernel<<<NTOK, 256>>>(out);
    cudaStreamWaitEvent(0, evEnd, 0);

    cudaEventDestroy(evFork);
    cudaEventDestroy(evScan);
    cudaEventDestroy(evW2);
    cudaEventDestroy(evEnd);
    cudaStreamDestroy(s2);
}

// round 17
// speedup vs baseline: 1.4885x; 1.0270x over previous
#include <cuda_runtime.h>
#include <cuda_fp16.h>
#include <cstdint>
#include <math.h>

#define NTOK 8192
#define NE   8
#define DDIM 1024
#define HDIM 5632
#define H2   (2*HDIM)
#define CAP  1280

#define OUT_AUX  8388608
#define OUT_TOP  (8388608 + 1)
#define OUT_KEEP (8388608 + 1 + NTOK)

#define NB1 88                     // gemm1 n-tiles per expert

// ---------------- scratch ----------------
__device__ float d_probs[NTOK * NE];
__device__ float d_z2[NTOK];
__device__ int   d_top[NTOK];
__device__ int   d_keep[NTOK];
__device__ int   d_gidx[NE * CAP];
__device__ int   d_counts[NE];
__device__ int   d_counts_cap[NE];
__device__ unsigned int d_hdone[NE * 10];
__device__ __align__(256) __half d_hh[(size_t)NE * CAP * HDIM];     // 115 MB
__device__ __align__(256) __half d_xh[(size_t)NTOK * DDIM];         //  17 MB
__device__ __align__(256) __half d_w13h[(size_t)NE * H2 * DDIM];    // 184 MB
__device__ __align__(256) __half d_w2h[(size_t)NE * DDIM * HDIM];   //  92 MB

// ---------------- helpers ----------------
__device__ __forceinline__ uint32_t smem_u32(const void* p) {
    uint32_t a;
    asm("{ .reg .u64 t; cvta.to.shared.u64 t, %1; cvt.u32.u64 %0, t; }"
        : "=r"(a) : "l"(p));
    return a;
}
__device__ __forceinline__ uint32_t h2_u32(__half2 h) {
    return *reinterpret_cast<uint32_t*>(&h);
}
__device__ __forceinline__ void mma_f16(float* c, const uint32_t* a,
                                        uint32_t b0, uint32_t b1) {
    asm volatile(
        "mma.sync.aligned.m16n8k16.row.col.f32.f16.f16.f32 "
        "{%0,%1,%2,%3}, {%4,%5,%6,%7}, {%8,%9}, {%0,%1,%2,%3};"
        : "+f"(c[0]), "+f"(c[1]), "+f"(c[2]), "+f"(c[3])
        : "r"(a[0]), "r"(a[1]), "r"(a[2]), "r"(a[3]), "r"(b0), "r"(b1));
}
#define LDSM4(r0, r1, r2, r3, a) \
    asm volatile("ldmatrix.sync.aligned.m8n8.x4.shared.b16 {%0,%1,%2,%3}, [%4];" \
                 : "=r"(r0), "=r"(r1), "=r"(r2), "=r"(r3) : "r"(a))
#define CP16(d, s) \
    asm volatile("cp.async.cg.shared.global [%0], [%1], 16;" :: "r"(d), "l"(s))
#define CPCOMMIT() asm volatile("cp.async.commit_group;")
#define CPWAIT1()  asm volatile("cp.async.wait_group 1;")

// ---------------- 0. fp32 -> fp16 conversion (4 float4 / thread) -----------
__global__ void cvt4_kernel(const float4* __restrict__ src,
                            uint2* __restrict__ dst, int n4)
{
    int base = blockIdx.x * 1024 + threadIdx.x;
#pragma unroll
    for (int k = 0; k < 4; k++) {
        int i = base + k * 256;
        if (i < n4) {
            float4 v = src[i];
            dst[i] = make_uint2(h2_u32(__floats2half2_rn(v.x, v.y)),
                                h2_u32(__floats2half2_rn(v.z, v.w)));
        }
    }
}

// ---------------- 1. router ----------------
__global__ void router_kernel(const float* __restrict__ x,
                              const float* __restrict__ Wg)
{
    __shared__ float sWg[NE * DDIM];
    int t = threadIdx.x;
    for (int i = t; i < NE * DDIM; i += 256) sWg[i] = Wg[i];
    __syncthreads();

    int warp = t >> 5, lane = t & 31;
    int tok  = blockIdx.x * 8 + warp;
    const float* xr = x + (size_t)tok * DDIM;

    float acc[NE];
#pragma unroll
    for (int e = 0; e < NE; e++) acc[e] = 0.f;
    for (int k = lane; k < DDIM; k += 32) {
        float xv = xr[k];
#pragma unroll
        for (int e = 0; e < NE; e++) acc[e] = fmaf(xv, sWg[e * DDIM + k], acc[e]);
    }
#pragma unroll
    for (int e = 0; e < NE; e++) {
#pragma unroll
        for (int o = 16; o > 0; o >>= 1)
            acc[e] += __shfl_down_sync(0xffffffffu, acc[e], o);
    }
    if (lane == 0) {
        float m = acc[0]; int am = 0;
#pragma unroll
        for (int e = 1; e < NE; e++) if (acc[e] > m) { m = acc[e]; am = e; }
        float p[NE]; float s = 0.f;
#pragma unroll
        for (int e = 0; e < NE; e++) { p[e] = expf(acc[e] - m); s += p[e]; }
        float inv = 1.f / s;
#pragma unroll
        for (int e = 0; e < NE; e++) d_probs[tok * NE + e] = p[e] * inv;
        float z = m + logf(s);
        d_z2[tok] = z * z;
        d_top[tok] = am;
    }
}

// ---------------- 2. ordered capacity scan + counter reset ----------------
__global__ void scan_kernel()
{
    __shared__ unsigned long long wsum0[32], wsum1[32];
    __shared__ unsigned long long tile0, tile1;
    __shared__ int base[NE];
    const int t = threadIdx.x, lane = t & 31, wid = t >> 5;
    if (t < NE) base[t] = 0;
    if (t < NE * 10) d_hdone[t] = 0;
    __syncthreads();

    for (int tile = 0; tile < NTOK / 1024; tile++) {
        int i = tile * 1024 + t;
        int e = d_top[i];
        unsigned long long v0 = (e < 4)  ? (1ULL << (16 * e))       : 0ULL;
        unsigned long long v1 = (e >= 4) ? (1ULL << (16 * (e - 4))) : 0ULL;
        unsigned long long s0 = v0, s1 = v1;
#pragma unroll
        for (int o = 1; o < 32; o <<= 1) {
            unsigned long long a0 = __shfl_up_sync(0xffffffffu, s0, o);
            unsigned long long a1 = __shfl_up_sync(0xffffffffu, s1, o);
            if (lane >= o) { s0 += a0; s1 += a1; }
        }
        if (lane == 31) { wsum0[wid] = s0; wsum1[wid] = s1; }
        __syncthreads();
        if (wid == 0) {
            unsigned long long w0 = wsum0[lane], w1 = wsum1[lane];
            unsigned long long p0 = w0, p1 = w1;
#pragma unroll
            for (int o = 1; o < 32; o <<= 1) {
                unsigned long long a0 = __shfl_up_sync(0xffffffffu, p0, o);
                unsigned long long a1 = __shfl_up_sync(0xffffffffu, p1, o);
                if (lane >= o) { p0 += a0; p1 += a1; }
            }
            wsum0[lane] = p0 - w0;
            wsum1[lane] = p1 - w1;
            if (lane == 31) { tile0 = p0; tile1 = p1; }
        }
        __syncthreads();
        unsigned long long inc = (e < 4) ? (s0 + wsum0[wid]) : (s1 + wsum1[wid]);
        int sh  = 16 * (e & 3);
        int pos = base[e] + (int)((inc >> sh) & 0xFFFFULL) - 1;
        int kp  = (pos < CAP) ? 1 : 0;
        d_keep[i] = kp;
        if (kp) d_gidx[e * CAP + pos] = i;
        __syncthreads();
        if (t < 4)      base[t] += (int)((tile0 >> (16 * t)) & 0xFFFFULL);
        else if (t < 8) base[t] += (int)((tile1 >> (16 * (t - 4))) & 0xFFFFULL);
        __syncthreads();
    }
    if (t < NE) {
        d_counts[t] = base[t];
        d_counts_cap[t] = base[t] < CAP ? base[t] : CAP;
    }
}

// ---------------- 3. aux loss ----------------
__global__ void reduce_kernel(float* __restrict__ out_aux)
{
    __shared__ float sm[1024];
    __shared__ float pe[NE];
    int t = threadIdx.x;
    float pp[NE];
#pragma unroll
    for (int e = 0; e < NE; e++) pp[e] = 0.f;
    float zz = 0.f;
    for (int i = t; i < NTOK; i += 1024) {
#pragma unroll
        for (int e = 0; e < NE; e++) pp[e] += d_probs[i * NE + e];
        zz += d_z2[i];
    }
#pragma unroll
    for (int e = 0; e < NE; e++) {
        sm[t] = pp[e]; __syncthreads();
        for (int o = 512; o > 0; o >>= 1) {
            if (t < o) sm[t] += sm[t + o];
            __syncthreads();
        }
        if (t == 0) pe[e] = sm[0];
        __syncthreads();
    }
    sm[t] = zz; __syncthreads();
    for (int o = 512; o > 0; o >>= 1) {
        if (t < o) sm[t] += sm[t + o];
        __syncthreads();
    }
    if (t == 0) {
        float bal = 0.f;
        for (int e = 0; e < NE; e++)
            bal += (pe[e] / (float)NTOK) * ((float)d_counts[e] / (float)NTOK);
        bal *= 0.01f * (float)NE;
        out_aux[0] = bal + (sm[0] / (float)NTOK) * 0.001f;
    }
}

// ---------------- 4. fused GEMM: z<8 = gemm1(e=z); z==8 = gemm2 ------------
// All input weights (w13h, w2h) are ready before launch (event-gated), so the
// ONLY runtime dependency is gemm2 -> gemm1's h tiles, tracked by d_hdone and
// satisfied intra-grid: producers have strictly lower bids, so every resident
// spinning consumer waits on running-or-finished blocks (deadlock-free).
#define STG_B  32768
#define SMEM_G (3 * STG_B)

__global__ __launch_bounds__(256, 2)
void moe_gemm_fused(float* __restrict__ out)
{
    extern __shared__ char smc[];
    __shared__ int s_tok[128];

    const int t = threadIdx.x, wid = t >> 5, lane = t & 31;
    const int lc = lane & 3;
    const int warpM = wid & 3, warpN = wid >> 2;

    int mode, e, mb, nb;
    if (blockIdx.z < 8) {
        mode = 0; e = blockIdx.z; mb = blockIdx.x; nb = blockIdx.y;
    } else {
        int id = blockIdx.y * 10 + blockIdx.x;
        if (id >= 640) return;
        mode = 1; e = id / 80; nb = (id % 80) / 10; mb = id % 10;
    }

    const int cc = d_counts_cap[e];
    const int m0 = mb * 128;
    if (m0 >= cc) return;            // dead rows: never read (both modes)

    if (t < 128)
        s_tok[t] = (m0 + t < cc) ? d_gidx[e * CAP + m0 + t] : ((mode == 0) ? 0 : -1);
    if (mode == 1 && t == 0) {
        volatile const unsigned int* hp = &d_hdone[e * 10 + mb];
        while (*hp < NB1) __nanosleep(128);
        __threadfence();
    }
    __syncthreads();

    const uint32_t sbase = smem_u32(smc);
    const int lrow = t >> 1;
    const int q0l  = (t & 1) * 4;

    const int KT  = (mode == 0) ? DDIM / 64 : HDIM / 64;
    const int WNS = (mode == 0) ? 32 : 64;
    const int NO2 = (mode == 0) ? 64 : 32;

    auto load_stage = [&](int kt, int s) {
        const uint32_t ab = sbase + (uint32_t)s * STG_B;
        const uint32_t bb = ab + 16384;
        const int k0 = kt * 64;
#pragma unroll
        for (int c = 0; c < 4; c++) {
            int q = q0l + c;
            uint32_t dsw = (uint32_t)(lrow * 128 + ((q ^ (lrow & 7)) << 4));
            const __half* srcA;
            if (mode == 0)
                srcA = d_xh + (size_t)s_tok[lrow] * DDIM + k0 + q * 8;
            else
                srcA = d_hh + ((size_t)e * CAP + m0 + lrow) * HDIM + k0 + q * 8;
            CP16(ab + dsw, srcA);
            const __half* srcB;
            if (mode == 0) {
                int wr = (lrow < 64) ? (nb * 64 + lrow)
                                     : (HDIM + nb * 64 + lrow - 64);
                srcB = d_w13h + ((size_t)e * H2 + wr) * DDIM + k0 + q * 8;
            } else {
                srcB = d_w2h + ((size_t)e * DDIM + nb * 128 + lrow) * HDIM + k0 + q * 8;
            }
            CP16(bb + dsw, srcB);
        }
    };

    float c0[2][4][4], c1[2][4][4];
#pragma unroll
    for (int a = 0; a < 2; a++)
#pragma unroll
        for (int b = 0; b < 4; b++)
#pragma unroll
            for (int r = 0; r < 4; r++) { c0[a][b][r] = 0.f; c1[a][b][r] = 0.f; }

    const int rA  = warpM * 32 + (lane & 15);
    const int cselA = lane >> 4;
    const int rB  = (lane & 7) + ((lane & 16) >> 1);
    const int cselB = (lane >> 3) & 1;

    load_stage(0, 0); CPCOMMIT();
    load_stage(1, 1); CPCOMMIT();

    for (int kt = 0; kt < KT; kt++) {
        CPWAIT1();
        __syncthreads();
        if (kt + 2 < KT) load_stage(kt + 2, (kt + 2) % 3);
        CPCOMMIT();

        const uint32_t ab = sbase + (uint32_t)(kt % 3) * STG_B;
        const uint32_t bb = ab + 16384;
#pragma unroll
        for (int kk = 0; kk < 4; kk++) {
            uint32_t a[2][4];
#pragma unroll
            for (int mf = 0; mf < 2; mf++) {
                int r = rA + mf * 16;
                uint32_t ad = ab + r * 128 + (((kk * 2 + cselA) ^ (r & 7)) << 4);
                LDSM4(a[mf][0], a[mf][1], a[mf][2], a[mf][3], ad);
            }
#pragma unroll
            for (int p = 0; p < 2; p++) {
                int r0n = warpN * WNS + p * 16 + rB;
                uint32_t bd0 = bb + r0n * 128 + (((kk * 2 + cselB) ^ (r0n & 7)) << 4);
                uint32_t g0, g1, g2, g3;
                LDSM4(g0, g1, g2, g3, bd0);
                int r1n = r0n + NO2;
                uint32_t bd1 = bb + r1n * 128 + (((kk * 2 + cselB) ^ (r1n & 7)) << 4);
                uint32_t u0, u1, u2, u3;
                LDSM4(u0, u1, u2, u3, bd1);
#pragma unroll
                for (int mf = 0; mf < 2; mf++) {
                    mma_f16(c0[mf][2 * p],     a[mf], g0, g1);
                    mma_f16(c0[mf][2 * p + 1], a[mf], g2, g3);
                    mma_f16(c1[mf][2 * p],     a[mf], u0, u1);
                    mma_f16(c1[mf][2 * p + 1], a[mf], u2, u3);
                }
            }
        }
    }

    const int lr = lane >> 2;
    if (mode == 0) {
#pragma unroll
        for (int mf = 0; mf < 2; mf++) {
            int r0 = m0 + warpM * 32 + mf * 16 + lr;
#pragma unroll
            for (int nf = 0; nf < 4; nf++) {
                int col = nb * 64 + warpN * 32 + nf * 8 + 2 * lc;
#pragma unroll
                for (int hh = 0; hh < 2; hh++) {
                    float g0 = c0[mf][nf][2 * hh], g1 = c0[mf][nf][2 * hh + 1];
                    float u0 = c1[mf][nf][2 * hh], u1 = c1[mf][nf][2 * hh + 1];
                    float h0 = g0 * u0 / (1.f + expf(-g0));
                    float h1 = g1 * u1 / (1.f + expf(-g1));
                    __half2 hv = __floats2half2_rn(h0, h1);
                    *(__half2*)(d_hh + ((size_t)e * CAP + r0 + 8 * hh) * HDIM + col) = hv;
                }
            }
        }
        __threadfence();
        __syncthreads();
        if (t == 0) atomicAdd(&d_hdone[e * 10 + mb], 1u);
    } else {
#pragma unroll
        for (int mf = 0; mf < 2; mf++) {
            int rl = warpM * 32 + mf * 16 + lr;
            int tok0 = s_tok[rl], tok1 = s_tok[rl + 8];
#pragma unroll
            for (int nf = 0; nf < 4; nf++) {
                int colA = nb * 128 + warpN * 64 + nf * 8 + 2 * lc;
                int colB = colA + 32;
                if (tok0 >= 0) {
                    *(float2*)(out + (size_t)tok0 * DDIM + colA) =
                        make_float2(c0[mf][nf][0], c0[mf][nf][1]);
                    *(float2*)(out + (size_t)tok0 * DDIM + colB) =
                        make_float2(c1[mf][nf][0], c1[mf][nf][1]);
                }
                if (tok1 >= 0) {
                    *(float2*)(out + (size_t)tok1 * DDIM + colA) =
                        make_float2(c0[mf][nf][2], c0[mf][nf][3]);
                    *(float2*)(out + (size_t)tok1 * DDIM + colB) =
                        make_float2(c1[mf][nf][2], c1[mf][nf][3]);
                }
            }
        }
    }
}

// ---------------- 6. finalize ----------------
__global__ void finalize_kernel(float* __restrict__ out)
{
    int i = blockIdx.x, t = threadIdx.x;
    int kp = d_keep[i];
    if (!kp)
        ((float4*)(out + (size_t)i * DDIM))[t] = make_float4(0.f, 0.f, 0.f, 0.f);
    if (t == 0) {
        out[OUT_TOP + i]  = (float)d_top[i];
        out[OUT_KEEP + i] = kp ? 1.f : 0.f;
    }
}

// ---------------- launch ----------------
extern "C" void kernel_launch(void* const* d_in, const int* in_sizes, int n_in,
                              void* d_out, int out_size)
{
    const float* x   = (const float*)d_in[0];
    const float* Wg  = (const float*)d_in[1];
    const float* W13 = (const float*)d_in[2];
    const float* W2  = (const float*)d_in[3];
    float* out = (float*)d_out;

    cudaFuncSetAttribute(moe_gemm_fused, cudaFuncAttributeMaxDynamicSharedMemorySize, SMEM_G);

    __half* xh;   cudaGetSymbolAddress((void**)&xh,   d_xh);
    __half* w13h; cudaGetSymbolAddress((void**)&w13h, d_w13h);
    __half* w2h;  cudaGetSymbolAddress((void**)&w2h,  d_w2h);

    const int n4x  = NTOK * DDIM / 4;
    const int n4w1 = NE * H2 * DDIM / 4;
    const int n4w2 = NE * DDIM * HDIM / 4;

    cudaStream_t s2;
    cudaEvent_t evFork, evJoin1, evW2, evEnd;
    cudaStreamCreateWithFlags(&s2, cudaStreamNonBlocking);
    cudaEventCreateWithFlags(&evFork,  cudaEventDisableTiming);
    cudaEventCreateWithFlags(&evJoin1, cudaEventDisableTiming);
    cudaEventCreateWithFlags(&evW2,    cudaEventDisableTiming);
    cudaEventCreateWithFlags(&evEnd,   cudaEventDisableTiming);

    cudaEventRecord(evFork, 0);
    cudaStreamWaitEvent(s2, evFork, 0);

    // side stream: token path (scan resets hdone), W2 cvt, small kernels
    cvt4_kernel<<<(n4x + 1023) / 1024, 256, 0, s2>>>((const float4*)x, (uint2*)xh, n4x);
    router_kernel<<<NTOK / 8, 256, 0, s2>>>(x, Wg);
    scan_kernel<<<1, 1024, 0, s2>>>();
    cvt4_kernel<<<(n4w2 + 1023) / 1024, 256, 0, s2>>>((const float4*)W2, (uint2*)w2h, n4w2);
    cudaEventRecord(evW2, s2);               // covers scan + xh + w2h
    reduce_kernel<<<1, 1024, 0, s2>>>(out + OUT_AUX);
    finalize_kernel<<<NTOK, 256, 0, s2>>>(out);
    cudaEventRecord(evEnd, s2);

    // main stream: W13 conversion, then fused GEMM (all deps via events)
    cvt4_kernel<<<(n4w1 + 1023) / 1024, 256>>>((const float4*)W13, (uint2*)w13h, n4w1);

    cudaStreamWaitEvent(0, evW2, 0);
    dim3 gf(10, 88, 9);
    moe_gemm_fused<<<gf, 256, SMEM_G>>>(out);

    cudaStreamWaitEvent(0, evEnd, 0);

    cudaEventDestroy(evFork);
    cudaEventDestroy(evJoin1);
    cudaEventDestroy(evW2);
    cudaEventDestroy(evEnd);
    cudaStreamDestroy(s2);
}